// round 6
// baseline (speedup 1.0000x reference)
#include <cuda_runtime.h>
#include <cstdint>

#define BQ    64
#define DIMS  256
#define RDEG  32
#define EF    32
#define KOUT  10
#define NPTS  100000
#define VIS_WORDS ((NPTS + 31) / 32)   // 3125

#define NB_NDB   1   // workers arrive (ndb ready), warp 0 waits
#define NB_WORK  2   // warp 0 arrives (nbid/freshm ready), workers wait

typedef unsigned long long u64;

static __device__ __forceinline__ void bar_arrive_named(int id) {
    asm volatile("bar.arrive %0, %1;" :: "r"(id), "r"(1024) : "memory");
}
static __device__ __forceinline__ void bar_wait_named(int id) {
    asm volatile("bar.sync %0, %1;" :: "r"(id), "r"(1024) : "memory");
}

__device__ __forceinline__ u64 shfl_xor64(u64 v, int m) {
    return __shfl_xor_sync(0xffffffffu, v, m);
}
__device__ __forceinline__ u64 u64min(u64 a, u64 b) { return a < b ? a : b; }
__device__ __forceinline__ u64 u64max(u64 a, u64 b) { return a > b ? a : b; }

// One compare-exchange stage of a bitonic network on a per-lane u64 key.
#define BSTAGE(v, kk, jj) {                                        \
    u64 _o = shfl_xor64(v, jj);                                    \
    bool _up    = ((lane & (kk)) == 0);                            \
    bool _lower = ((lane & (jj)) == 0);                            \
    v = (_up == _lower) ? u64min(v, _o) : u64max(v, _o); }

// Full ascending bitonic sort of 32 u64 keys (one per lane), 15 stages.
#define SORT32(v) {                                                \
    BSTAGE(v, 2, 1);                                               \
    BSTAGE(v, 4, 2);  BSTAGE(v, 4, 1);                             \
    BSTAGE(v, 8, 4);  BSTAGE(v, 8, 2);  BSTAGE(v, 8, 1);           \
    BSTAGE(v, 16, 8); BSTAGE(v, 16, 4); BSTAGE(v, 16, 2); BSTAGE(v, 16, 1); \
    BSTAGE(v, 32, 16);BSTAGE(v, 32, 8); BSTAGE(v, 32, 4); BSTAGE(v, 32, 2); BSTAGE(v, 32, 1); }

// Warp-collective squared distance (binary-tree fp32 sum, matches XLA tree reduce).
__device__ __forceinline__ float warp_sqdist(const float* __restrict__ storage,
                                             int id, float4 b0, float4 b1, int lane) {
    const float4* row = (const float4*)(storage + (size_t)id * DIMS);
    float4 a0 = row[lane], a1 = row[lane + 32];
    float d0 = a0.x - b0.x, d1 = a0.y - b0.y, d2 = a0.z - b0.z, d3 = a0.w - b0.w;
    float e0 = a1.x - b1.x, e1 = a1.y - b1.y, e2 = a1.z - b1.z, e3 = a1.w - b1.w;
    float s = ((d0 * d0 + d1 * d1) + (d2 * d2 + d3 * d3))
            + ((e0 * e0 + e1 * e1) + (e2 * e2 + e3 * e3));
#pragma unroll
    for (int o = 16; o; o >>= 1) s += __shfl_xor_sync(0xffffffffu, s, o);
    return s;
}

// Two distances with loads issued up-front (for the double-duty worker warp).
__device__ __forceinline__ void warp_sqdist2(const float* __restrict__ storage,
                                             int idA, int idB, bool cA, bool cB,
                                             float4 q0, float4 q1, int lane,
                                             float& sA, float& sB) {
    float4 z = make_float4(0.f, 0.f, 0.f, 0.f);
    float4 a0 = z, a1 = z, b0 = z, b1 = z;
    if (cA) { const float4* r = (const float4*)(storage + (size_t)idA * DIMS);
              a0 = r[lane]; a1 = r[lane + 32]; }
    if (cB) { const float4* r = (const float4*)(storage + (size_t)idB * DIMS);
              b0 = r[lane]; b1 = r[lane + 32]; }
    float d0 = a0.x - q0.x, d1 = a0.y - q0.y, d2 = a0.z - q0.z, d3 = a0.w - q0.w;
    float e0 = a1.x - q1.x, e1 = a1.y - q1.y, e2 = a1.z - q1.z, e3 = a1.w - q1.w;
    float f0 = b0.x - q0.x, f1 = b0.y - q0.y, f2 = b0.z - q0.z, f3 = b0.w - q0.w;
    float g0 = b1.x - q1.x, g1 = b1.y - q1.y, g2 = b1.z - q1.z, g3 = b1.w - q1.w;
    float x = ((d0*d0 + d1*d1) + (d2*d2 + d3*d3)) + ((e0*e0 + e1*e1) + (e2*e2 + e3*e3));
    float y = ((f0*f0 + f1*f1) + (f2*f2 + f3*f3)) + ((g0*g0 + g1*g1) + (g2*g2 + g3*g3));
#pragma unroll
    for (int o = 16; o; o >>= 1) {
        x += __shfl_xor_sync(0xffffffffu, x, o);
        y += __shfl_xor_sync(0xffffffffu, y, o);
    }
    sA = x; sB = y;
}

__global__ __launch_bounds__(1024, 1)
void nsw_search_kernel(const float* __restrict__ query,
                       const float* __restrict__ storage,
                       const int*   __restrict__ graph,
                       const int*   __restrict__ initial,
                       float*       __restrict__ out) {
    __shared__ unsigned int vis[VIS_WORDS];   // visited bitset (warp0-owned after init)
    __shared__ int          nbid[RDEG];
    __shared__ unsigned int freshm[RDEG];
    __shared__ unsigned int ndb[RDEG];
    __shared__ int          initids[EF];
    __shared__ unsigned int initdb[EF];

    const int b    = blockIdx.x;
    const int tid  = threadIdx.x;
    const int w    = tid >> 5;
    const int lane = tid & 31;
    const unsigned int INFB = __float_as_uint(1e30f);

    const float4* qrow = (const float4*)(query + (size_t)b * DIMS);
    const float4 q0 = qrow[lane], q1 = qrow[lane + 32];

    // ---- init ----
    for (int i = tid; i < VIS_WORDS; i += 1024) vis[i] = 0u;
    if (w == 0) initids[lane] = __ldg(initial + b * EF + lane);
    __syncthreads();

    {   // initial candidate distances: warp w -> initids[w]
        float s = warp_sqdist(storage, initids[w], q0, q1, lane);
        if (lane == 0) initdb[w] = __float_as_uint(s);
    }
    if (w == 1) {   // visited[init] = True
        int id = initids[lane];
        atomicOr(&vis[id >> 5], 1u << (id & 31));
    }
    if (w == 2) {   // L2-warm graph rows of all init candidates (1 line each)
        const int* gp = graph + (size_t)initids[lane] * RDEG;
        asm volatile("prefetch.global.L2 [%0];" :: "l"(gp));
    }
    __syncthreads();

    u64 ka = 0;     // sorted pool key: dist(32)|rank(6)@25|id(17)@1|exp(1)@0
    int cur_nb = 0; // this lane's published neighbor id (register copy of nbid[lane])
    if (w == 0) {
        // bootstrap: keys from the unsorted initial pool, slot = original index
        ka = ((u64)initdb[lane] << 32) | ((u64)(unsigned)lane << 25)
           | ((u64)(unsigned)initids[lane] << 1);
        u64 mk = ka;
#pragma unroll
        for (int o = 16; o; o >>= 1) mk = u64min(mk, shfl_xor64(mk, o));
        const int u  = (int)((mk >> 1) & 0x1FFFFu);
        const int nb = __ldg(graph + (size_t)u * RDEG + lane);   // overlaps the sort
        SORT32(ka);
        {   // rebuild: slot = sorted rank; exp for id == u
            unsigned int d = (unsigned int)(ka >> 32);
            int id = (int)((ka >> 1) & 0x1FFFFu);
            unsigned int e = (id == u) ? 1u : 0u;
            ka = ((u64)d << 32) | ((u64)(unsigned)lane << 25) | ((u64)(unsigned)id << 1) | e;
        }
        // fresh reads for ALL neighbors before any visited write
        unsigned int word  = vis[nb >> 5];
        unsigned int fresh = ((word >> (nb & 31)) & 1u) ^ 1u;
        __syncwarp();
        nbid[lane]   = nb;
        freshm[lane] = fresh;
        cur_nb = nb;
        atomicOr(&vis[nb >> 5], 1u << (nb & 31));
    }
    __syncthreads();   // step-0 work published to workers

    if (w == 0) {
        // ============ sorter warp ============
        for (int t = 0; t < EF; ++t) {
            bar_wait_named(NB_NDB);          // ndb[t] ready
            u64 kb = ((u64)ndb[lane] << 32) | ((u64)(unsigned)(lane + 32) << 25)
                   | ((u64)(unsigned)cur_nb << 1);               // exp = 0
            const bool more = (t < EF - 1);
            int u = 0;
            if (more) {
                // pick next u before the merge (min-key unexpanded always survives)
                u64 mk = u64min((ka & 1ull) ? ~0ull : ka, kb);
#pragma unroll
                for (int o = 16; o; o >>= 1) mk = u64min(mk, shfl_xor64(mk, o));
                u = (int)((mk >> 1) & 0x1FFFFu);
                int nb = __ldg(graph + (size_t)u * RDEG + lane); // L2-hot (prefetched)
                unsigned int word  = vis[nb >> 5];
                unsigned int fresh = ((word >> (nb & 31)) & 1u) ^ 1u;
                __syncwarp();                 // all fresh reads before any vis write
                nbid[lane]   = nb;
                freshm[lane] = fresh;
                cur_nb = nb;
                bar_arrive_named(NB_WORK);    // release workers for step t+1
                atomicOr(&vis[nb >> 5], 1u << (nb & 31));  // warp0-private state
            }
            // sort neighbors + top-32 merge (overlaps workers' next distances)
            SORT32(kb);
            u64 lo = u64min(ka, shfl_xor64(kb, 31));
#pragma unroll
            for (int j = 16; j >= 1; j >>= 1) {
                u64 o = shfl_xor64(lo, j);
                lo = ((lane & j) == 0) ? u64min(lo, o) : u64max(lo, o);
            }
            {   // rebuild sorted pool; mark exp for id == u_next
                unsigned int d = (unsigned int)(lo >> 32);
                int id = (int)((lo >> 1) & 0x1FFFFu);
                unsigned int e = (unsigned int)(lo & 1ull);
                if (more && id == u) e = 1u;
                ka = ((u64)d << 32) | ((u64)(unsigned)lane << 25)
                   | ((u64)(unsigned)id << 1) | e;
            }
        }
        // ---- output: top_k(-cd, 10) == first 10 of the sorted pool ----
        if (lane < KOUT) {
            out[b * KOUT + lane]             = (float)((ka >> 1) & 0x1FFFFu);
            out[BQ * KOUT + b * KOUT + lane] = __uint_as_float((unsigned int)(ka >> 32));
        }
    } else {
        // ============ distance workers: warp w -> neighbor w-1 (warp 31 also 31) ====
        const int  n1   = w - 1;
        const bool dual = (w == 31);
        for (int t = 0; t < EF; ++t) {
            if (t) bar_wait_named(NB_WORK);   // nbid/freshm for step t ready
            int idA = nbid[n1];
            unsigned fA = freshm[n1];
            int idB = dual ? nbid[31] : 0;
            unsigned fB = dual ? freshm[31] : 0u;
            if (lane == 0) {   // warm the graph rows these neighbors would need as u
                asm volatile("prefetch.global.L2 [%0];"
                             :: "l"(graph + (size_t)idA * RDEG));
                if (dual)
                    asm volatile("prefetch.global.L2 [%0];"
                                 :: "l"(graph + (size_t)idB * RDEG));
            }
            unsigned rA = INFB, rB = INFB;
            if (!dual) {
                if (fA) rA = __float_as_uint(warp_sqdist(storage, idA, q0, q1, lane));
            } else {
                float sA, sB;
                warp_sqdist2(storage, idA, idB, fA != 0u, fB != 0u, q0, q1, lane, sA, sB);
                if (fA) rA = __float_as_uint(sA);
                if (fB) rB = __float_as_uint(sB);
            }
            if (lane == 0) { ndb[n1] = rA; if (dual) ndb[31] = rB; }
            bar_arrive_named(NB_NDB);
        }
    }
}

extern "C" void kernel_launch(void* const* d_in, const int* in_sizes, int n_in,
                              void* d_out, int out_size) {
    const float* query   = (const float*)d_in[0];
    const float* storage = (const float*)d_in[1];
    const int*   graph   = (const int*)d_in[2];
    const int*   initial = (const int*)d_in[3];
    (void)in_sizes; (void)n_in; (void)out_size;
    nsw_search_kernel<<<BQ, 1024>>>(query, storage, graph, initial, (float*)d_out);
}

// round 7
// speedup vs baseline: 1.2369x; 1.2369x over previous
#include <cuda_runtime.h>
#include <cstdint>

#define BQ    64
#define DIMS  256
#define RDEG  32
#define EF    32
#define KOUT  10
#define NPTS  100000
#define VIS_WORDS ((NPTS + 31) / 32)   // 3125

typedef unsigned long long u64;

__device__ __forceinline__ u64 shfl_xor64(u64 v, int m) {
    return __shfl_xor_sync(0xffffffffu, v, m);
}
__device__ __forceinline__ u64 u64min(u64 a, u64 b) { return a < b ? a : b; }
__device__ __forceinline__ u64 u64max(u64 a, u64 b) { return a > b ? a : b; }

// One compare-exchange stage of a bitonic network on a per-lane u64 key.
#define BSTAGE(v, kk, jj) {                                        \
    u64 _o = shfl_xor64(v, jj);                                    \
    bool _up    = ((lane & (kk)) == 0);                            \
    bool _lower = ((lane & (jj)) == 0);                            \
    v = (_up == _lower) ? u64min(v, _o) : u64max(v, _o); }

// Full ascending bitonic sort of 32 u64 keys (one per lane), 15 stages.
#define SORT32(v) {                                                \
    BSTAGE(v, 2, 1);                                               \
    BSTAGE(v, 4, 2);  BSTAGE(v, 4, 1);                             \
    BSTAGE(v, 8, 4);  BSTAGE(v, 8, 2);  BSTAGE(v, 8, 1);           \
    BSTAGE(v, 16, 8); BSTAGE(v, 16, 4); BSTAGE(v, 16, 2); BSTAGE(v, 16, 1); \
    BSTAGE(v, 32, 16);BSTAGE(v, 32, 8); BSTAGE(v, 32, 4); BSTAGE(v, 32, 2); BSTAGE(v, 32, 1); }

// Warp-collective squared distance (binary-tree fp32 sum, matches XLA tree reduce).
__device__ __forceinline__ float warp_sqdist(const float* __restrict__ storage,
                                             int id, float4 b0, float4 b1, int lane) {
    const float4* row = (const float4*)(storage + (size_t)id * DIMS);
    float4 a0 = row[lane], a1 = row[lane + 32];
    float d0 = a0.x - b0.x, d1 = a0.y - b0.y, d2 = a0.z - b0.z, d3 = a0.w - b0.w;
    float e0 = a1.x - b1.x, e1 = a1.y - b1.y, e2 = a1.z - b1.z, e3 = a1.w - b1.w;
    float s = ((d0 * d0 + d1 * d1) + (d2 * d2 + d3 * d3))
            + ((e0 * e0 + e1 * e1) + (e2 * e2 + e3 * e3));
#pragma unroll
    for (int o = 16; o; o >>= 1) s += __shfl_xor_sync(0xffffffffu, s, o);
    return s;
}

__global__ __launch_bounds__(1024, 1)
void nsw_search_kernel(const float* __restrict__ query,
                       const float* __restrict__ storage,
                       const int*   __restrict__ graph,
                       const int*   __restrict__ initial,
                       float*       __restrict__ out) {
    __shared__ unsigned int vis[VIS_WORDS];   // visited bitset, 12.5 KB
    __shared__ int          nbid[RDEG];       // neighbor ids of expanded node
    __shared__ unsigned int freshm[RDEG];     // neighbor freshness
    __shared__ unsigned int ndb[RDEG];        // neighbor dist bits
    __shared__ int          initids[EF];
    __shared__ unsigned int initdb[EF];

    const int b    = blockIdx.x;
    const int tid  = threadIdx.x;
    const int w    = tid >> 5;
    const int lane = tid & 31;
    const unsigned int INFB = __float_as_uint(1e30f);

    // Query vector lives in registers.
    const float4* qrow = (const float4*)(query + (size_t)b * DIMS);
    const float4 q0 = qrow[lane], q1 = qrow[lane + 32];

    // ---- init ----
    for (int i = tid; i < VIS_WORDS; i += 1024) vis[i] = 0u;
    if (w == 0) initids[lane] = __ldg(initial + b * EF + lane);
    __syncthreads();

    // initial candidate distances (warp w -> initids[w]); warp 1 marks visited;
    // warp 2 L2-warms all init graph rows (1 line each).
    {
        float s = warp_sqdist(storage, initids[w], q0, q1, lane);
        if (lane == 0) initdb[w] = __float_as_uint(s);
    }
    if (w == 1) {
        int id = initids[lane];
        atomicOr(&vis[id >> 5], 1u << (id & 31));        // visited[init] = True
    }
    if (w == 2) {
        asm volatile("prefetch.global.L2 [%0];"
                     :: "l"(graph + (size_t)initids[lane] * RDEG));
    }
    __syncthreads();

    u64 ka = 0;   // sorted candidate pool key: dist(32)|slot(6)@25|id(17)@1|exp(1)@0
    if (w == 0) {
        // keys from the (unsorted) initial pool; slot = original index (stability)
        ka = ((u64)initdb[lane] << 32) | ((u64)(unsigned)lane << 25)
           | ((u64)(unsigned)initids[lane] << 1);
        // pick u0 = argmin (all unexpanded)
        u64 mk = ka;
#pragma unroll
        for (int o = 16; o; o >>= 1) mk = u64min(mk, shfl_xor64(mk, o));
        const int u  = (int)((mk >> 1) & 0x1FFFFu);
        const int nb = __ldg(graph + (size_t)u * RDEG + lane);   // L2-warm
        // prefetch neighbor storage rows NOW: full-sort lead time before phase 2
        {
            const float* rp = storage + (size_t)nb * DIMS;
#pragma unroll
            for (int i = 0; i < 8; i++)
                asm volatile("prefetch.global.L2 [%0];" :: "l"(rp + i * 32));
        }
        // freshness: read for ALL neighbors before any visited write
        unsigned int word  = vis[nb >> 5];
        unsigned int fresh = ((word >> (nb & 31)) & 1u) ^ 1u;
        __syncwarp();
        nbid[lane]   = nb;
        freshm[lane] = fresh;
        atomicOr(&vis[nb >> 5], 1u << (nb & 31));
        // sort pool (top_k-stable order == (d, orig slot)) — overlaps prefetches
        SORT32(ka);
        {   // rebuild: slot = sorted rank; exp for id == u
            unsigned int d = (unsigned int)(ka >> 32);
            int id = (int)((ka >> 1) & 0x1FFFFu);
            unsigned int e = (id == u) ? 1u : 0u;
            ka = ((u64)d << 32) | ((u64)(unsigned)lane << 25) | ((u64)(unsigned)id << 1) | e;
        }
    }
    __syncthreads();

    // ---- ef_search expansion steps; pool stays sorted (== top_k order)
    for (int t = 0; t < EF; ++t) {
        // Phase 2 (all 32 warps): warp w computes distance to neighbor w.
        // Lane 0 also L2-warms the graph row this neighbor would need as next u.
        {
            int      idA = nbid[w];
            unsigned fA  = freshm[w];
            if (lane == 0)
                asm volatile("prefetch.global.L2 [%0];"
                             :: "l"(graph + (size_t)idA * RDEG));
            unsigned int res = INFB;
            if (fA) {
                float s = warp_sqdist(storage, idA, q0, q1, lane);
                res = __float_as_uint(s);
            }
            if (lane == 0) ndb[w] = res;
        }
        __syncthreads();

        // Phase 3 (warp 0): pick next u BEFORE the merge (min-key unexpanded
        // entry always survives into the top-32); graph row is L2-hot; issue
        // storage prefetches + publish next step's work, THEN sort+merge so the
        // prefetches get the whole sort as lead time.
        if (w == 0) {
            u64 kb = ((u64)ndb[lane] << 32) | ((u64)(unsigned)(lane + 32) << 25)
                   | ((u64)(unsigned)nbid[lane] << 1);           // exp = 0

            const bool more = (t < EF - 1);
            int u = 0;
            if (more) {
                u64 mk = u64min((ka & 1ull) ? ~0ull : ka, kb);   // mask expanded
#pragma unroll
                for (int o = 16; o; o >>= 1) mk = u64min(mk, shfl_xor64(mk, o));
                u = (int)((mk >> 1) & 0x1FFFFu);
                int nb = __ldg(graph + (size_t)u * RDEG + lane); // L2-hot
                {   // storage prefetch with ~full-sort lead time
                    const float* rp = storage + (size_t)nb * DIMS;
#pragma unroll
                    for (int i = 0; i < 8; i++)
                        asm volatile("prefetch.global.L2 [%0];" :: "l"(rp + i * 32));
                }
                // freshness reads before any visited write
                unsigned int word  = vis[nb >> 5];
                unsigned int fresh = ((word >> (nb & 31)) & 1u) ^ 1u;
                __syncwarp();
                nbid[lane]   = nb;     // kb already captured the old nbid value
                freshm[lane] = fresh;
                atomicOr(&vis[nb >> 5], 1u << (nb & 31));
            }

            // sort the 32 neighbor keys (pool ka is already sorted)
            SORT32(kb);
            // top-32 of two ascending 32-seqs: min vs reversed, then 5-stage merge
            u64 lo = u64min(ka, shfl_xor64(kb, 31));
#pragma unroll
            for (int j = 16; j >= 1; j >>= 1) {
                u64 o = shfl_xor64(lo, j);
                lo = ((lane & j) == 0) ? u64min(lo, o) : u64max(lo, o);
            }
            {   // rebuild sorted pool: slot = rank; mark exp for id == u_next
                unsigned int d = (unsigned int)(lo >> 32);
                int id = (int)((lo >> 1) & 0x1FFFFu);
                unsigned int e = (unsigned int)(lo & 1ull);
                if (more && id == u) e = 1u;
                ka = ((u64)d << 32) | ((u64)(unsigned)lane << 25)
                   | ((u64)(unsigned)id << 1) | e;
            }
        }
        __syncthreads();
    }

    // ---- output: final top_k(-cd, 10) == first 10 of the sorted pool ----
    // Tuple outputs flattened+concatenated: ids[B*K] then dists[B*K], as float32.
    if (w == 0 && lane < KOUT) {
        out[b * KOUT + lane]             = (float)((ka >> 1) & 0x1FFFFu);
        out[BQ * KOUT + b * KOUT + lane] = __uint_as_float((unsigned int)(ka >> 32));
    }
}

extern "C" void kernel_launch(void* const* d_in, const int* in_sizes, int n_in,
                              void* d_out, int out_size) {
    const float* query   = (const float*)d_in[0];
    const float* storage = (const float*)d_in[1];
    const int*   graph   = (const int*)d_in[2];
    const int*   initial = (const int*)d_in[3];
    (void)in_sizes; (void)n_in; (void)out_size;
    nsw_search_kernel<<<BQ, 1024>>>(query, storage, graph, initial, (float*)d_out);
}

// round 8
// speedup vs baseline: 1.5337x; 1.2400x over previous
#include <cuda_runtime.h>
#include <cstdint>

#define BQ    64
#define DIMS  256
#define RDEG  32
#define EF    32
#define KOUT  10
#define NPTS  100000
#define VIS_WORDS ((NPTS + 31) / 32)   // 3125

typedef unsigned long long u64;

__device__ __forceinline__ u64 shfl_xor64(u64 v, int m) {
    return __shfl_xor_sync(0xffffffffu, v, m);
}
__device__ __forceinline__ u64 u64min(u64 a, u64 b) { return a < b ? a : b; }
__device__ __forceinline__ u64 u64max(u64 a, u64 b) { return a > b ? a : b; }

// One compare-exchange stage of a bitonic network on a per-lane u64 key.
#define BSTAGE(v, kk, jj) {                                        \
    u64 _o = shfl_xor64(v, jj);                                    \
    bool _up    = ((lane & (kk)) == 0);                            \
    bool _lower = ((lane & (jj)) == 0);                            \
    v = (_up == _lower) ? u64min(v, _o) : u64max(v, _o); }

// Full ascending bitonic sort of 32 u64 keys (one per lane), 15 stages.
#define SORT32(v) {                                                \
    BSTAGE(v, 2, 1);                                               \
    BSTAGE(v, 4, 2);  BSTAGE(v, 4, 1);                             \
    BSTAGE(v, 8, 4);  BSTAGE(v, 8, 2);  BSTAGE(v, 8, 1);           \
    BSTAGE(v, 16, 8); BSTAGE(v, 16, 4); BSTAGE(v, 16, 2); BSTAGE(v, 16, 1); \
    BSTAGE(v, 32, 16);BSTAGE(v, 32, 8); BSTAGE(v, 32, 4); BSTAGE(v, 32, 2); BSTAGE(v, 32, 1); }

// Warp-collective squared distance (binary-tree fp32 sum, matches XLA tree reduce).
__device__ __forceinline__ float warp_sqdist(const float* __restrict__ storage,
                                             int id, float4 b0, float4 b1, int lane) {
    const float4* row = (const float4*)(storage + (size_t)id * DIMS);
    float4 a0 = row[lane], a1 = row[lane + 32];
    float d0 = a0.x - b0.x, d1 = a0.y - b0.y, d2 = a0.z - b0.z, d3 = a0.w - b0.w;
    float e0 = a1.x - b1.x, e1 = a1.y - b1.y, e2 = a1.z - b1.z, e3 = a1.w - b1.w;
    float s = ((d0 * d0 + d1 * d1) + (d2 * d2 + d3 * d3))
            + ((e0 * e0 + e1 * e1) + (e2 * e2 + e3 * e3));
#pragma unroll
    for (int o = 16; o; o >>= 1) s += __shfl_xor_sync(0xffffffffu, s, o);
    return s;
}

__global__ __launch_bounds__(1024, 1)
void nsw_search_kernel(const float* __restrict__ query,
                       const float* __restrict__ storage,
                       const int*   __restrict__ graph,
                       const int*   __restrict__ initial,
                       float*       __restrict__ out) {
    __shared__ unsigned int vis[VIS_WORDS];      // visited bitset, 12.5 KB
    __shared__ int          nbid[2][RDEG];       // neighbor ids, double-buffered by step parity
    __shared__ unsigned int freshm[2][RDEG];     // neighbor freshness, double-buffered
    __shared__ unsigned int ndb[RDEG];           // neighbor dist bits
    __shared__ u64          skb[RDEG];           // sorted neighbor keys (warp1 -> warp0)
    __shared__ int          initids[EF];
    __shared__ unsigned int initdb[EF];

    const int b    = blockIdx.x;
    const int tid  = threadIdx.x;
    const int w    = tid >> 5;
    const int lane = tid & 31;
    const unsigned int INFB = __float_as_uint(1e30f);

    // Query vector lives in registers.
    const float4* qrow = (const float4*)(query + (size_t)b * DIMS);
    const float4 q0 = qrow[lane], q1 = qrow[lane + 32];

    // ---- init ----
    for (int i = tid; i < VIS_WORDS; i += 1024) vis[i] = 0u;
    if (w == 0) initids[lane] = __ldg(initial + b * EF + lane);
    __syncthreads();

    // initial candidate distances (warp w -> initids[w]); warp 1 marks visited;
    // warp 2 L2-warms all init graph rows (1 line each).
    {
        float s = warp_sqdist(storage, initids[w], q0, q1, lane);
        if (lane == 0) initdb[w] = __float_as_uint(s);
    }
    if (w == 1) {
        int id = initids[lane];
        atomicOr(&vis[id >> 5], 1u << (id & 31));        // visited[init] = True
    }
    if (w == 2) {
        asm volatile("prefetch.global.L2 [%0];"
                     :: "l"(graph + (size_t)initids[lane] * RDEG));
    }
    __syncthreads();

    u64 ka = 0;   // sorted candidate pool key: dist(32)|slot(6)@25|id(17)@1|exp(1)@0
    if (w == 0) {
        // keys from the (unsorted) initial pool; slot = original index (stability)
        ka = ((u64)initdb[lane] << 32) | ((u64)(unsigned)lane << 25)
           | ((u64)(unsigned)initids[lane] << 1);
        // pick u0 = argmin (all unexpanded); graph LDG overlaps the sort (R5 order)
        u64 mk = ka;
#pragma unroll
        for (int o = 16; o; o >>= 1) mk = u64min(mk, shfl_xor64(mk, o));
        const int u  = (int)((mk >> 1) & 0x1FFFFu);
        const int nb = __ldg(graph + (size_t)u * RDEG + lane);
        SORT32(ka);
        {   // rebuild: slot = sorted rank; exp for id == u
            unsigned int d = (unsigned int)(ka >> 32);
            int id = (int)((ka >> 1) & 0x1FFFFu);
            unsigned int e = (id == u) ? 1u : 0u;
            ka = ((u64)d << 32) | ((u64)(unsigned)lane << 25) | ((u64)(unsigned)id << 1) | e;
        }
        {   // storage prefetch for step-0 neighbors
            const float* rp = storage + (size_t)nb * DIMS;
#pragma unroll
            for (int i = 0; i < 8; i++)
                asm volatile("prefetch.global.L2 [%0];" :: "l"(rp + i * 32));
        }
        // freshness: read for ALL neighbors before any visited write
        unsigned int word  = vis[nb >> 5];
        unsigned int fresh = ((word >> (nb & 31)) & 1u) ^ 1u;
        __syncwarp();
        nbid[0][lane]   = nb;
        freshm[0][lane] = fresh;
        atomicOr(&vis[nb >> 5], 1u << (nb & 31));
    }
    __syncthreads();

    // ---- ef_search expansion steps; pool stays sorted (== top_k order)
    for (int t = 0; t < EF; ++t) {
        const int par = t & 1;

        // Phase 2 (all 32 warps): warp w computes distance to neighbor w.
        // Lane 0 also L2-warms that node's graph row (candidate next-u).
        {
            int      idA = nbid[par][w];
            unsigned fA  = freshm[par][w];
            if (lane == 0)
                asm volatile("prefetch.global.L2 [%0];"
                             :: "l"(graph + (size_t)idA * RDEG));
            unsigned int res = INFB;
            if (fA) {
                float s = warp_sqdist(storage, idA, q0, q1, lane);
                res = __float_as_uint(s);
            }
            if (lane == 0) ndb[w] = res;
        }
        __syncthreads();

        const bool more = (t < EF - 1);

        if (w == 1) {
            // ---- sort path: sort the 32 neighbor keys, hand off via smem ----
            u64 kb = ((u64)ndb[lane] << 32) | ((u64)(unsigned)(lane + 32) << 25)
                   | ((u64)(unsigned)nbid[par][lane] << 1);      // exp = 0
            SORT32(kb);
            skb[lane] = kb;
            asm volatile("bar.sync 3, 64;" ::: "memory");        // meet warp 0
        } else if (w == 0) {
            // ---- pick path: next u, graph row, prefetch, publish (parallel w/ sort)
            int u = 0;
            if (more) {
                u64 kb = ((u64)ndb[lane] << 32) | ((u64)(unsigned)(lane + 32) << 25)
                       | ((u64)(unsigned)nbid[par][lane] << 1);
                // min-key unexpanded always survives into the top-32 -> safe pre-pick
                u64 mk = u64min((ka & 1ull) ? ~0ull : ka, kb);
#pragma unroll
                for (int o = 16; o; o >>= 1) mk = u64min(mk, shfl_xor64(mk, o));
                u = (int)((mk >> 1) & 0x1FFFFu);
                int nb = __ldg(graph + (size_t)u * RDEG + lane); // L2-hot
                {   // storage prefetch: lead time = rest of sort + merge + barrier
                    const float* rp = storage + (size_t)nb * DIMS;
#pragma unroll
                    for (int i = 0; i < 8; i++)
                        asm volatile("prefetch.global.L2 [%0];" :: "l"(rp + i * 32));
                }
                // freshness reads before any visited write
                unsigned int word  = vis[nb >> 5];
                unsigned int fresh = ((word >> (nb & 31)) & 1u) ^ 1u;
                __syncwarp();
                nbid[par ^ 1][lane]   = nb;      // other parity: no race w/ warp 1
                freshm[par ^ 1][lane] = fresh;
                atomicOr(&vis[nb >> 5], 1u << (nb & 31));
            }
            asm volatile("bar.sync 3, 64;" ::: "memory");        // sorted keys ready

            // top-32 of two ascending 32-seqs: min vs reversed (direct smem index),
            // then 5-stage bitonic cleanup.
            u64 lo = u64min(ka, skb[lane ^ 31]);
#pragma unroll
            for (int j = 16; j >= 1; j >>= 1) {
                u64 o = shfl_xor64(lo, j);
                lo = ((lane & j) == 0) ? u64min(lo, o) : u64max(lo, o);
            }
            {   // rebuild sorted pool: slot = rank; mark exp for id == u_next
                unsigned int d = (unsigned int)(lo >> 32);
                int id = (int)((lo >> 1) & 0x1FFFFu);
                unsigned int e = (unsigned int)(lo & 1ull);
                if (more && id == u) e = 1u;
                ka = ((u64)d << 32) | ((u64)(unsigned)lane << 25)
                   | ((u64)(unsigned)id << 1) | e;
            }
        }
        __syncthreads();
    }

    // ---- output: final top_k(-cd, 10) == first 10 of the sorted pool ----
    // Tuple outputs flattened+concatenated: ids[B*K] then dists[B*K], as float32.
    if (w == 0 && lane < KOUT) {
        out[b * KOUT + lane]             = (float)((ka >> 1) & 0x1FFFFu);
        out[BQ * KOUT + b * KOUT + lane] = __uint_as_float((unsigned int)(ka >> 32));
    }
}

extern "C" void kernel_launch(void* const* d_in, const int* in_sizes, int n_in,
                              void* d_out, int out_size) {
    const float* query   = (const float*)d_in[0];
    const float* storage = (const float*)d_in[1];
    const int*   graph   = (const int*)d_in[2];
    const int*   initial = (const int*)d_in[3];
    (void)in_sizes; (void)n_in; (void)out_size;
    nsw_search_kernel<<<BQ, 1024>>>(query, storage, graph, initial, (float*)d_out);
}